// round 16
// baseline (speedup 1.0000x reference)
#include <cuda_runtime.h>
#include <cuda_bf16.h>
#include <math.h>
#include <cstdint>

#define BN 16
#define LL 1024
#define TOK (BN*LL)          // 16384 tokens
#define DM 256
#define DI 512
#define DS 16
#define DTR 16
#define NPROJ 48             // DTR + 2*DS
#define NSEG 32
#define SEGL (LL/NSEG)       // 32

// ---------------- scratch (device globals; no allocation allowed) ------------
__device__ float g_h[TOK*DM];        // residual stream (b, l, m)
__device__ float g_xz[TOK*2*DI];     // in_proj output: [0:DI)=xin, [DI:2DI)=z
__device__ float g_u[TOK*DI];        // conv+silu output (f32, for scan)
__device__ float g_proj[TOK*NPROJ];  // x_proj output: dt | B | C
__device__ float g_hseg[BN*NSEG*DI*DS];   // pass1 local final states
__device__ float g_hinit[BN*NSEG*DI*DS];  // combined segment initial states
__device__ float g_sumd[BN*NSEG*DI];      // per-segment sum of delta

__device__ __align__(256) __nv_bfloat16 g_xn_bf[TOK*DM];   // LN output (GEMM A)
__device__ __align__(256) __nv_bfloat16 g_u_bf[TOK*DI];    // conv output (GEMM A)
__device__ __align__(256) __nv_bfloat16 g_y_bf[TOK*DI];    // scan output (GEMM A)
__device__ __align__(256) __nv_bfloat16 g_inw_bf[4*1024*256];
__device__ __align__(256) __nv_bfloat16 g_xpw_bf[4*128*512];  // padded 48->128
__device__ __align__(256) __nv_bfloat16 g_outw_bf[4*256*512];

// ---------------- helpers ----------------------------------------------------
__device__ __forceinline__ float sigmoidf_(float x) {
    return 1.f / (1.f + __expf(-x));
}
__device__ __forceinline__ float softplus_fast_(float x) {
    return (x > 20.f) ? x : __logf(1.f + __expf(x));
}
__device__ __forceinline__ uint32_t smem_u32_(const void* p) {
    uint32_t a;
    asm("{ .reg .u64 t; cvta.to.shared.u64 t, %1; cvt.u32.u64 %0, t; }" : "=r"(a) : "l"(p));
    return a;
}
__device__ __forceinline__ uint32_t bf2_(float lo, float hi) {
    uint32_t r;
    asm("cvt.rn.bf16x2.f32 %0, %1, %2;" : "=r"(r) : "f"(hi), "f"(lo));
    return r;
}
#define LDSM4_(r0,r1,r2,r3,addr) \
    asm volatile("ldmatrix.sync.aligned.m8n8.x4.shared.b16 {%0,%1,%2,%3}, [%4];" \
        : "=r"(r0),"=r"(r1),"=r"(r2),"=r"(r3) : "r"(addr))
__device__ __forceinline__ void mma_bf16_(float* c, const uint32_t* a, const uint32_t* b) {
    asm volatile(
        "mma.sync.aligned.m16n8k16.row.col.f32.bf16.bf16.f32 "
        "{%0,%1,%2,%3}, {%4,%5,%6,%7}, {%8,%9}, {%0,%1,%2,%3};"
        : "+f"(c[0]), "+f"(c[1]), "+f"(c[2]), "+f"(c[3])
        : "r"(a[0]), "r"(a[1]), "r"(a[2]), "r"(a[3]), "r"(b[0]), "r"(b[1]));
}

// e[s] = q^(s+1) for s=0..15 via power tree
__device__ __forceinline__ void powers16_(float q, float* e) {
    float q2 = q*q, q4 = q2*q2, q8 = q4*q4;
    e[0]=q;      e[1]=q2;      e[2]=q2*q;    e[3]=q4;
    e[4]=q4*q;   e[5]=q4*q2;   e[6]=e[5]*q;  e[7]=q8;
    e[8]=q8*q;   e[9]=q8*q2;   e[10]=e[9]*q; e[11]=q8*q4;
    e[12]=e[11]*q; e[13]=e[11]*q2; e[14]=e[13]*q; e[15]=q8*q8;
}

// ---------------- bf16 GEMM w/ cp.async: C[M,N] = A[M,K] @ W[N,K]^T ----------
#define GBM 128
#define GBK 32
#define PITCH 80u
#define TILE_B (128u*PITCH)
#define STAGE_B (2u*TILE_B)
#define NSTAGE 3
#define GEMM_SMEM (NSTAGE*STAGE_B)

template<int NROWS>
__device__ __forceinline__ void cp_tile_(const __nv_bfloat16* __restrict__ G, int ld,
                                         int row0, int k0, uint32_t sb, int tid) {
    #pragma unroll
    for (int i = 0; i < NROWS/64; i++) {
        int cid = tid + i * 256;
        int row = cid >> 2;
        int c = cid & 3;
        uint32_t dst = sb + (uint32_t)row * PITCH + (uint32_t)c * 16u;
        const void* src = G + (size_t)(row0 + row) * ld + k0 + c * 8;
        asm volatile("cp.async.ca.shared.global [%0], [%1], 16;" :: "r"(dst), "l"(src));
    }
}

template<int EPI, int GN>
__global__ __launch_bounds__(256, 2) void mma_gemm_kernel(
        const __nv_bfloat16* __restrict__ A, int lda,
        const __nv_bfloat16* __restrict__ W,
        float* __restrict__ C, int ldc,
        int K, int NW) {
    constexpr int NF = GN / 32;
    extern __shared__ char smem[];
    uint32_t sbase = smem_u32_(smem);
    int tid = threadIdx.x;
    int wid = tid >> 5, lane = tid & 31;
    int g = lane >> 2, tg = lane & 3;
    int bm = blockIdx.y * GBM;
    int bn = blockIdx.x * GN;
    int wm0 = (wid & 1) * 64;
    int wn0 = (wid >> 1) * (GN / 4);

    int rr = (lane & 7) + ((lane >> 3) & 1) * 8;
    int cc = (lane >> 4);

    float acc[4][NF][4];
    #pragma unroll
    for (int mf = 0; mf < 4; mf++)
        #pragma unroll
        for (int nf = 0; nf < NF; nf++)
            #pragma unroll
            for (int r = 0; r < 4; r++) acc[mf][nf][r] = 0.f;

    const int nst = K / GBK;

    #pragma unroll
    for (int p = 0; p < NSTAGE - 1; p++) {
        uint32_t sb = sbase + (uint32_t)p * STAGE_B;
        cp_tile_<128>(A, lda, bm, p * GBK, sb, tid);
        cp_tile_<GN>(W, K,   bn, p * GBK, sb + TILE_B, tid);
        asm volatile("cp.async.commit_group;" ::: "memory");
    }

    for (int s = 0; s < nst; s++) {
        asm volatile("cp.async.wait_group 1;" ::: "memory");
        __syncthreads();
        uint32_t Sa = sbase + (uint32_t)(s % NSTAGE) * STAGE_B;
        uint32_t Sw = Sa + TILE_B;

        #pragma unroll
        for (int kk = 0; kk < 2; kk++) {
            uint32_t chunk_off = (uint32_t)(kk * 2 + cc) * 16u;
            uint32_t afr[4][4], bfr[NF][2];
            #pragma unroll
            for (int mf = 0; mf < 4; mf++) {
                uint32_t ad = Sa + (uint32_t)(wm0 + mf * 16 + rr) * PITCH + chunk_off;
                LDSM4_(afr[mf][0], afr[mf][1], afr[mf][2], afr[mf][3], ad);
            }
            #pragma unroll
            for (int nh = 0; nh < NF/2; nh++) {
                uint32_t bd = Sw + (uint32_t)(wn0 + nh * 16 + rr) * PITCH + chunk_off;
                LDSM4_(bfr[2*nh][0], bfr[2*nh+1][0], bfr[2*nh][1], bfr[2*nh+1][1], bd);
            }
            #pragma unroll
            for (int mf = 0; mf < 4; mf++)
                #pragma unroll
                for (int nf = 0; nf < NF; nf++)
                    mma_bf16_(acc[mf][nf], afr[mf], bfr[nf]);
        }

        if (s + 2 < nst) {
            uint32_t nb = sbase + (uint32_t)((s + 2) % NSTAGE) * STAGE_B;
            cp_tile_<128>(A, lda, bm, (s + 2) * GBK, nb, tid);
            cp_tile_<GN>(W, K,   bn, (s + 2) * GBK, nb + TILE_B, tid);
        }
        asm volatile("cp.async.commit_group;" ::: "memory");
    }

    #pragma unroll
    for (int mf = 0; mf < 4; mf++) {
        int gr = bm + wm0 + mf * 16 + g;
        #pragma unroll
        for (int nf = 0; nf < NF; nf++) {
            int gc = bn + wn0 + nf * 8 + 2 * tg;
            if (gc >= NW) continue;
            float2 v01 = make_float2(acc[mf][nf][0], acc[mf][nf][1]);
            float2 v23 = make_float2(acc[mf][nf][2], acc[mf][nf][3]);
            float* p0 = C + (size_t)gr * ldc + gc;
            float* p1 = C + (size_t)(gr + 8) * ldc + gc;
            if (EPI == 2) {
                float2 o0 = *reinterpret_cast<float2*>(p0);
                float2 o1 = *reinterpret_cast<float2*>(p1);
                v01.x += o0.x; v01.y += o0.y;
                v23.x += o1.x; v23.y += o1.y;
            }
            *reinterpret_cast<float2*>(p0) = v01;
            *reinterpret_cast<float2*>(p1) = v23;
        }
    }
}

// ---------------- weight conversion (all layers) -----------------------------
#define INW_E  (4*1024*256)
#define XPW_E  (4*128*512)
#define OUTW_E (4*256*512)
__global__ void wconv_kernel(const float* __restrict__ in_w,
                             const float* __restrict__ xpw,
                             const float* __restrict__ out_w) {
    int i = blockIdx.x * 256 + threadIdx.x;
    if (i < INW_E) {
        g_inw_bf[i] = __float2bfloat16(in_w[i]);
        return;
    }
    int j = i - INW_E;
    if (j < XPW_E) {
        int layer = j >> 16;
        int r = (j >> 9) & 127;
        int c = j & 511;
        float v = (r < NPROJ) ? xpw[((size_t)layer * NPROJ + r) * 512 + c] : 0.f;
        g_xpw_bf[j] = __float2bfloat16(v);
        return;
    }
    int k = j - XPW_E;
    if (k < OUTW_E) g_outw_bf[k] = __float2bfloat16(out_w[k]);
}

// ---------------- stem conv (k=3, pad=1) + relu ------------------------------
__global__ void stem_kernel(const float* __restrict__ x,
                            const float* __restrict__ sw,
                            const float* __restrict__ sb) {
    int t = blockIdx.x;
    int m = threadIdx.x;
    int b = t / LL, l = t % LL;
    __shared__ float xs[3][3];
    if (m < 9) {
        int c = m / 3, k = m % 3;
        int ll = l - 1 + k;
        xs[c][k] = (ll >= 0 && ll < LL) ? x[(b*3 + c)*LL + ll] : 0.f;
    }
    __syncthreads();
    float acc = sb[m];
    #pragma unroll
    for (int c = 0; c < 3; c++)
        #pragma unroll
        for (int k = 0; k < 3; k++)
            acc = fmaf(xs[c][k], sw[(m*3 + c)*3 + k], acc);
    g_h[t*DM + m] = fmaxf(acc, 0.f);
}

// ---------------- layernorm -> bf16, warp-per-token --------------------------
__device__ __forceinline__ float warp_sum_(float v) {
    #pragma unroll
    for (int o = 16; o; o >>= 1) v += __shfl_xor_sync(0xffffffffu, v, o);
    return v;
}
__global__ __launch_bounds__(256) void ln_kernel(const float* __restrict__ in,
                                                 const float* __restrict__ g,
                                                 const float* __restrict__ b) {
    int wid = threadIdx.x >> 5, lane = threadIdx.x & 31;
    int t = blockIdx.x * 8 + wid;
    const float* row = in + (size_t)t * DM + lane * 8;
    float4 v0 = *reinterpret_cast<const float4*>(row);
    float4 v1 = *reinterpret_cast<const float4*>(row + 4);
    float s = v0.x+v0.y+v0.z+v0.w + v1.x+v1.y+v1.z+v1.w;
    float mean = warp_sum_(s) * (1.f / DM);
    float d0 = v0.x-mean, d1 = v0.y-mean, d2 = v0.z-mean, d3 = v0.w-mean;
    float d4 = v1.x-mean, d5 = v1.y-mean, d6 = v1.z-mean, d7 = v1.w-mean;
    float q = d0*d0+d1*d1+d2*d2+d3*d3+d4*d4+d5*d5+d6*d6+d7*d7;
    float rstd = rsqrtf(warp_sum_(q) * (1.f / DM) + 1e-5f);
    float4 g0 = *reinterpret_cast<const float4*>(g + lane * 8);
    float4 g1 = *reinterpret_cast<const float4*>(g + lane * 8 + 4);
    float4 b0 = *reinterpret_cast<const float4*>(b + lane * 8);
    float4 b1 = *reinterpret_cast<const float4*>(b + lane * 8 + 4);
    uint4 o;
    o.x = bf2_(d0*rstd*g0.x + b0.x, d1*rstd*g0.y + b0.y);
    o.y = bf2_(d2*rstd*g0.z + b0.z, d3*rstd*g0.w + b0.w);
    o.z = bf2_(d4*rstd*g1.x + b1.x, d5*rstd*g1.y + b1.y);
    o.w = bf2_(d6*rstd*g1.z + b1.z, d7*rstd*g1.w + b1.w);
    *reinterpret_cast<uint4*>(g_xn_bf + (size_t)t * DM + lane * 8) = o;
}

// ---------------- causal depthwise conv (k=4) + silu, float4 over d ----------
// one thread = 4 consecutive d at one token; 16B loads/stores (1/4 wavefronts)
__global__ __launch_bounds__(256) void conv_silu_kernel(const float* __restrict__ cw,
                                                        const float* __restrict__ cb) {
    int idx = blockIdx.x * 256 + threadIdx.x;     // 0 .. TOK*DI/4
    int dq = idx & (DI/4 - 1);                    // d/4
    int t  = idx >> 7;                            // DI/4 = 128
    int d  = dq * 4;
    int l  = t & (LL - 1);
    float4 acc = *reinterpret_cast<const float4*>(cb + d);
    #pragma unroll
    for (int k = 0; k < 4; k++) {
        int ls = l - 3 + k;
        if (ls >= 0) {
            float4 xv = *reinterpret_cast<const float4*>(
                g_xz + (size_t)(t - 3 + k) * (2*DI) + d);
            acc.x = fmaf(xv.x, cw[(d+0)*4 + k], acc.x);
            acc.y = fmaf(xv.y, cw[(d+1)*4 + k], acc.y);
            acc.z = fmaf(xv.z, cw[(d+2)*4 + k], acc.z);
            acc.w = fmaf(xv.w, cw[(d+3)*4 + k], acc.w);
        }
    }
    float4 r;
    r.x = acc.x * sigmoidf_(acc.x);
    r.y = acc.y * sigmoidf_(acc.y);
    r.z = acc.z * sigmoidf_(acc.z);
    r.w = acc.w * sigmoidf_(acc.w);
    *reinterpret_cast<float4*>(g_u + (size_t)t * DI + d) = r;
    uint2 o;
    o.x = bf2_(r.x, r.y);
    o.y = bf2_(r.z, r.w);
    *reinterpret_cast<uint2*>(g_u_bf + (size_t)t * DI + d) = o;
}

// ---------------- scan pass 1: local scans + fused delta ---------------------
// grid (DI/256, BN, NSEG), 256 threads; thread-per-d, SEGL=32 (4 chunks of 8).
__global__ __launch_bounds__(256) void scan1_kernel(const float* __restrict__ Alog,
                                                    const float* __restrict__ dtw,
                                                    const float* __restrict__ dtb) {
    int d = blockIdx.x * 256 + threadIdx.x;
    int b = blockIdx.y;
    int seg = blockIdx.z;
    int tid = threadIdx.x;

    float A[DS], wdt[DTR];
    bool fast = true;
    #pragma unroll
    for (int s4 = 0; s4 < DS; s4 += 4) {
        float4 av = *reinterpret_cast<const float4*>(Alog + d*DS + s4);
        A[s4] = -__expf(av.x); A[s4+1] = -__expf(av.y);
        A[s4+2] = -__expf(av.z); A[s4+3] = -__expf(av.w);
        fast = fast && fabsf(A[s4] + (float)(s4+1)) < 1e-3f
                    && fabsf(A[s4+1] + (float)(s4+2)) < 1e-3f
                    && fabsf(A[s4+2] + (float)(s4+3)) < 1e-3f
                    && fabsf(A[s4+3] + (float)(s4+4)) < 1e-3f;
    }
    fast = __all_sync(0xffffffffu, fast);
    #pragma unroll
    for (int r4 = 0; r4 < DTR; r4 += 4) {
        float4 wv = *reinterpret_cast<const float4*>(dtw + d*DTR + r4);
        wdt[r4] = wv.x; wdt[r4+1] = wv.y; wdt[r4+2] = wv.z; wdt[r4+3] = wv.w;
    }
    float bdt = dtb[d];

    float h[DS];
    #pragma unroll
    for (int s = 0; s < DS; s++) h[s] = 0.f;
    float sumd = 0.f;

    int t0 = b * LL + seg * SEGL;
    __shared__ float sD[8][DTR];
    __shared__ float sB[8][DS];

    for (int c0 = 0; c0 < SEGL; c0 += 8) {
        {   // 8 steps x 32 floats (dt | B) = 256 floats, 1/thread
            int step = tid >> 5, j = tid & 31;
            float val = g_proj[(size_t)(t0 + c0 + step)*NPROJ + j];
            if (j < DTR) sD[step][j] = val;
            else         sB[step][j - DTR] = val;
        }
        __syncthreads();
        float uc[8];
        #pragma unroll
        for (int i = 0; i < 8; i++)
            uc[i] = g_u[(size_t)(t0 + c0 + i)*DI + d];
        #pragma unroll
        for (int i = 0; i < 8; i++) {
            float draw = bdt;
            #pragma unroll
            for (int r = 0; r < DTR; r++) draw = fmaf(sD[i][r], wdt[r], draw);
            float dlt = softplus_fast_(draw);
            float du = dlt * uc[i];
            sumd += dlt;
            float e[DS];
            if (fast) powers16_(__expf(-dlt), e);
            else {
                #pragma unroll
                for (int s = 0; s < DS; s++) e[s] = __expf(dlt * A[s]);
            }
            #pragma unroll
            for (int s = 0; s < DS; s++)
                h[s] = fmaf(h[s], e[s], du * sB[i][s]);
        }
        __syncthreads();
    }

    size_t idx = ((size_t)b * NSEG + seg) * DI + d;
    float* H = g_hseg + idx * DS;
    #pragma unroll
    for (int s4 = 0; s4 < DS; s4 += 4)
        *reinterpret_cast<float4*>(H + s4) =
            make_float4(h[s4], h[s4+1], h[s4+2], h[s4+3]);
    g_sumd[idx] = sumd;
}

// ---------------- scan combine: prefix over segments -------------------------
__global__ __launch_bounds__(256) void scomb_kernel(const float* __restrict__ Alog) {
    int i = blockIdx.x * 256 + threadIdx.x;
    int b = i >> 9, d = i & 511;

    float A[DS];
    bool fast = true;
    #pragma unroll
    for (int s4 = 0; s4 < DS; s4 += 4) {
        float4 av = *reinterpret_cast<const float4*>(Alog + d*DS + s4);
        A[s4] = -__expf(av.x); A[s4+1] = -__expf(av.y);
        A[s4+2] = -__expf(av.z); A[s4+3] = -__expf(av.w);
        fast = fast && fabsf(A[s4] + (float)(s4+1)) < 1e-3f
                    && fabsf(A[s4+1] + (float)(s4+2)) < 1e-3f
                    && fabsf(A[s4+2] + (float)(s4+3)) < 1e-3f
                    && fabsf(A[s4+3] + (float)(s4+4)) < 1e-3f;
    }
    fast = __all_sync(0xffffffffu, fast);

    float carry[DS];
    #pragma unroll
    for (int s = 0; s < DS; s++) carry[s] = 0.f;

    for (int j = 0; j < NSEG; j++) {
        size_t idx = ((size_t)b * NSEG + j) * DI + d;
        float* I = g_hinit + idx * DS;
        #pragma unroll
        for (int s4 = 0; s4 < DS; s4 += 4)
            *reinterpret_cast<float4*>(I + s4) =
                make_float4(carry[s4], carry[s4+1], carry[s4+2], carry[s4+3]);
        float sd = g_sumd[idx];
        float e[DS];
        if (fast) powers16_(__expf(-sd), e);
        else {
            #pragma unroll
            for (int s = 0; s < DS; s++) e[s] = __expf(sd * A[s]);
        }
        const float* H = g_hseg + idx * DS;
        #pragma unroll
        for (int s4 = 0; s4 < DS; s4 += 4) {
            float4 hv = *reinterpret_cast<const float4*>(H + s4);
            carry[s4]   = fmaf(carry[s4],   e[s4],   hv.x);
            carry[s4+1] = fmaf(carry[s4+1], e[s4+1], hv.y);
            carry[s4+2] = fmaf(carry[s4+2], e[s4+2], hv.z);
            carry[s4+3] = fmaf(carry[s4+3], e[s4+3], hv.w);
        }
    }
}

// ---------------- scan pass 2: rescan from h_init, recompute delta, emit y ---
__global__ __launch_bounds__(256) void scan2_kernel(const float* __restrict__ Alog,
                                                    const float* __restrict__ Dp,
                                                    const float* __restrict__ dtw,
                                                    const float* __restrict__ dtb) {
    int d = blockIdx.x * 256 + threadIdx.x;
    int b = blockIdx.y;
    int seg = blockIdx.z;
    int tid = threadIdx.x;

    float A[DS], wdt[DTR];
    bool fast = true;
    #pragma unroll
    for (int s4 = 0; s4 < DS; s4 += 4) {
        float4 av = *reinterpret_cast<const float4*>(Alog + d*DS + s4);
        A[s4] = -__expf(av.x); A[s4+1] = -__expf(av.y);
        A[s4+2] = -__expf(av.z); A[s4+3] = -__expf(av.w);
        fast = fast && fabsf(A[s4] + (float)(s4+1)) < 1e-3f
                    && fabsf(A[s4+1] + (float)(s4+2)) < 1e-3f
                    && fabsf(A[s4+2] + (float)(s4+3)) < 1e-3f
                    && fabsf(A[s4+3] + (float)(s4+4)) < 1e-3f;
    }
    fast = __all_sync(0xffffffffu, fast);
    #pragma unroll
    for (int r4 = 0; r4 < DTR; r4 += 4) {
        float4 wv = *reinterpret_cast<const float4*>(dtw + d*DTR + r4);
        wdt[r4] = wv.x; wdt[r4+1] = wv.y; wdt[r4+2] = wv.z; wdt[r4+3] = wv.w;
    }
    float bdt = dtb[d];
    float Dd = Dp[d];

    float h[DS];
    {
        size_t idx = ((size_t)b * NSEG + seg) * DI + d;
        const float* I = g_hinit + idx * DS;
        #pragma unroll
        for (int s4 = 0; s4 < DS; s4 += 4) {
            float4 hv = *reinterpret_cast<const float4*>(I + s4);
            h[s4] = hv.x; h[s4+1] = hv.y; h[s4+2] = hv.z; h[s4+3] = hv.w;
        }
    }

    int t0 = b * LL + seg * SEGL;
    __shared__ float sP[8][NPROJ];   // dt | B | C rows

    for (int c0 = 0; c0 < SEGL; c0 += 8) {
        #pragma unroll
        for (int r = 0; r < 2; r++) {
            int i = tid + r * 256;   // 0..511, need 384
            if (i < 8 * NPROJ) {
                int step = i / NPROJ;
                int j = i - step * NPROJ;
                sP[step][j] = g_proj[(size_t)(t0 + c0 + step)*NPROJ + j];
            }
        }
        __syncthreads();
        float uc[8], zc[8];
        #pragma unroll
        for (int i = 0; i < 8; i++) {
            size_t t = (size_t)(t0 + c0 + i);
            uc[i] = g_u[t*DI + d];
            zc[i] = g_xz[t*2*DI + DI + d];
        }
        #pragma unroll
        for (int i = 0; i < 8; i++) {
            float draw = bdt;
            #pragma unroll
            for (int r = 0; r < DTR; r++) draw = fmaf(sP[i][r], wdt[r], draw);
            float dlt = softplus_fast_(draw);
            float uu = uc[i];
            float du = dlt * uu;
            float e[DS];
            if (fast) powers16_(__expf(-dlt), e);
            else {
                #pragma unroll
                for (int s = 0; s < DS; s++) e[s] = __expf(dlt * A[s]);
            }
            const float* Brow = &sP[i][DTR];
            const float* Crow = &sP[i][DTR + DS];
            float y = 0.f;
            #pragma unroll
            for (int s = 0; s < DS; s++) {
                h[s] = fmaf(h[s], e[s], du * Brow[s]);
                y = fmaf(h[s], Crow[s], y);
            }
            y = fmaf(uu, Dd, y);
            float zz = zc[i];
            y *= zz * sigmoidf_(zz);
            g_y_bf[(size_t)(t0 + c0 + i)*DI + d] = __float2bfloat16(y);
        }
        __syncthreads();
    }
}

// ---------------- final LN + head projection + sigmoid (warp/token) ----------
__global__ __launch_bounds__(256) void head_kernel(const float* __restrict__ g,
                                                   const float* __restrict__ b,
                                                   const float* __restrict__ hw,
                                                   const float* __restrict__ hb,
                                                   float* __restrict__ out) {
    int wid = threadIdx.x >> 5, lane = threadIdx.x & 31;
    int t = blockIdx.x * 8 + wid;
    const float* row = g_h + (size_t)t * DM + lane * 8;
    float4 v0 = *reinterpret_cast<const float4*>(row);
    float4 v1 = *reinterpret_cast<const float4*>(row + 4);
    float s = v0.x+v0.y+v0.z+v0.w + v1.x+v1.y+v1.z+v1.w;
    float mean = warp_sum_(s) * (1.f / DM);
    float d0 = v0.x-mean, d1 = v0.y-mean, d2 = v0.z-mean, d3 = v0.w-mean;
    float d4 = v1.x-mean, d5 = v1.y-mean, d6 = v1.z-mean, d7 = v1.w-mean;
    float q = d0*d0+d1*d1+d2*d2+d3*d3+d4*d4+d5*d5+d6*d6+d7*d7;
    float rstd = rsqrtf(warp_sum_(q) * (1.f / DM) + 1e-5f);
    float4 g0 = *reinterpret_cast<const float4*>(g + lane * 8);
    float4 g1 = *reinterpret_cast<const float4*>(g + lane * 8 + 4);
    float4 b0 = *reinterpret_cast<const float4*>(b + lane * 8);
    float4 b1 = *reinterpret_cast<const float4*>(b + lane * 8 + 4);
    float4 w0 = *reinterpret_cast<const float4*>(hw + lane * 8);
    float4 w1 = *reinterpret_cast<const float4*>(hw + lane * 8 + 4);
    float dot =
        (d0*rstd*g0.x + b0.x)*w0.x + (d1*rstd*g0.y + b0.y)*w0.y +
        (d2*rstd*g0.z + b0.z)*w0.z + (d3*rstd*g0.w + b0.w)*w0.w +
        (d4*rstd*g1.x + b1.x)*w1.x + (d5*rstd*g1.y + b1.y)*w1.y +
        (d6*rstd*g1.z + b1.z)*w1.z + (d7*rstd*g1.w + b1.w)*w1.w;
    float tot = warp_sum_(dot);
    if (lane == 0) out[t] = sigmoidf_(tot + hb[0]);
}

// ---------------- host launcher ----------------------------------------------
extern "C" void kernel_launch(void* const* d_in, const int* in_sizes, int n_in,
                              void* d_out, int out_size) {
    const float* x       = (const float*)d_in[0];
    const float* stem_w  = (const float*)d_in[1];
    const float* stem_b  = (const float*)d_in[2];
    const float* norm_g  = (const float*)d_in[3];
    const float* norm_b  = (const float*)d_in[4];
    const float* in_w    = (const float*)d_in[5];
    const float* conv_w  = (const float*)d_in[6];
    const float* conv_b  = (const float*)d_in[7];
    const float* xpw     = (const float*)d_in[8];
    const float* dtw     = (const float*)d_in[9];
    const float* dtb     = (const float*)d_in[10];
    const float* A_log   = (const float*)d_in[11];
    const float* Dp      = (const float*)d_in[12];
    const float* out_w   = (const float*)d_in[13];
    const float* fn_g    = (const float*)d_in[14];
    const float* fn_b    = (const float*)d_in[15];
    const float* head_w  = (const float*)d_in[16];
    const float* head_b  = (const float*)d_in[17];
    float* out = (float*)d_out;

    float *p_h, *p_xz, *p_u, *p_proj;
    __nv_bfloat16 *p_xn_bf, *p_u_bf, *p_y_bf, *p_inw, *p_xpw, *p_outw;
    cudaGetSymbolAddress((void**)&p_h,     g_h);
    cudaGetSymbolAddress((void**)&p_xz,    g_xz);
    cudaGetSymbolAddress((void**)&p_u,     g_u);
    cudaGetSymbolAddress((void**)&p_proj,  g_proj);
    cudaGetSymbolAddress((void**)&p_xn_bf, g_xn_bf);
    cudaGetSymbolAddress((void**)&p_u_bf,  g_u_bf);
    cudaGetSymbolAddress((void**)&p_y_bf,  g_y_bf);
    cudaGetSymbolAddress((void**)&p_inw,   g_inw_bf);
    cudaGetSymbolAddress((void**)&p_xpw,   g_xpw_bf);
    cudaGetSymbolAddress((void**)&p_outw,  g_outw_bf);

    cudaFuncSetAttribute((const void*)mma_gemm_kernel<0,128>,
                         cudaFuncAttributeMaxDynamicSharedMemorySize, GEMM_SMEM);
    cudaFuncSetAttribute((const void*)mma_gemm_kernel<2,128>,
                         cudaFuncAttributeMaxDynamicSharedMemorySize, GEMM_SMEM);
    cudaFuncSetAttribute((const void*)mma_gemm_kernel<0,64>,
                         cudaFuncAttributeMaxDynamicSharedMemorySize, GEMM_SMEM);

    wconv_kernel<<<(INW_E + XPW_E + OUTW_E)/256, 256>>>(in_w, xpw, out_w);
    stem_kernel<<<TOK, 256>>>(x, stem_w, stem_b);

    for (int i = 0; i < 4; i++) {
        ln_kernel<<<TOK/8, 256>>>(p_h, norm_g + i*DM, norm_b + i*DM);

        // in_proj: [TOK,1024] = xn @ W^T
        {
            dim3 grid((2*DI)/128, TOK/GBM);
            mma_gemm_kernel<0,128><<<grid, 256, GEMM_SMEM>>>(
                p_xn_bf, DM, p_inw + (size_t)i*1024*256, p_xz, 2*DI, DM, 2*DI);
        }

        conv_silu_kernel<<<(TOK*DI/4)/256, 256>>>(conv_w + (size_t)i*DI*4,
                                                  conv_b + (size_t)i*DI);

        // x_proj: [TOK,48] = u @ xw^T (64-wide tile, W padded rows)
        {
            dim3 grid(1, TOK/GBM);
            mma_gemm_kernel<0,64><<<grid, 256, GEMM_SMEM>>>(
                p_u_bf, DI, p_xpw + (size_t)i*128*512, p_proj, NPROJ, DI, NPROJ);
        }

        // chunked parallel scan: pass1 (fused delta) -> combine -> pass2
        {
            dim3 grid1(DI/256, BN, NSEG);
            scan1_kernel<<<grid1, 256>>>(A_log + (size_t)i*DI*DS,
                                         dtw + (size_t)i*DI*DTR,
                                         dtb + (size_t)i*DI);
            scomb_kernel<<<BN*DI/256, 256>>>(A_log + (size_t)i*DI*DS);
            scan2_kernel<<<grid1, 256>>>(A_log + (size_t)i*DI*DS, Dp + (size_t)i*DI,
                                         dtw + (size_t)i*DI*DTR,
                                         dtb + (size_t)i*DI);
        }

        // out proj + residual: h += y @ ow^T
        {
            dim3 grid(DM/128, TOK/GBM);
            mma_gemm_kernel<2,128><<<grid, 256, GEMM_SMEM>>>(
                p_y_bf, DI, p_outw + (size_t)i*256*512, p_h, DM, DI, DM);
        }
    }

    head_kernel<<<TOK/8, 256>>>(fn_g, fn_b, head_w, head_b, out);
    (void)in_sizes; (void)n_in; (void)out_size;
}

// round 17
// speedup vs baseline: 1.2290x; 1.2290x over previous
#include <cuda_runtime.h>
#include <cuda_bf16.h>
#include <math.h>
#include <cstdint>

#define BN 16
#define LL 1024
#define TOK (BN*LL)          // 16384 tokens
#define DM 256
#define DI 512
#define DS 16
#define DTR 16
#define NPROJ 48             // DTR + 2*DS
#define NSEG 32
#define SEGL (LL/NSEG)       // 32

// ---------------- scratch (device globals; no allocation allowed) ------------
__device__ float g_h[TOK*DM];        // residual stream (b, l, m)
__device__ float g_xz[TOK*2*DI];     // in_proj output: [0:DI)=xin, [DI:2DI)=z
__device__ float g_u[TOK*DI];        // conv+silu output (f32, for scan)
__device__ float g_proj[TOK*NPROJ];  // x_proj output: dt | B | C
__device__ float g_delta[TOK*DI];    // delta (computed in scan1, reused scan2)
__device__ float g_hseg[BN*NSEG*DI*DS];   // pass1 local final states
__device__ float g_hinit[BN*NSEG*DI*DS];  // combined segment initial states
__device__ float g_sumd[BN*NSEG*DI];      // per-segment sum of delta

__device__ __align__(256) __nv_bfloat16 g_xn_bf[TOK*DM];   // LN output (GEMM A)
__device__ __align__(256) __nv_bfloat16 g_u_bf[TOK*DI];    // conv output (GEMM A)
__device__ __align__(256) __nv_bfloat16 g_y_bf[TOK*DI];    // scan output (GEMM A)
__device__ __align__(256) __nv_bfloat16 g_inw_bf[4*1024*256];
__device__ __align__(256) __nv_bfloat16 g_xpw_bf[4*128*512];  // padded 48->128
__device__ __align__(256) __nv_bfloat16 g_outw_bf[4*256*512];

// ---------------- helpers ----------------------------------------------------
__device__ __forceinline__ float sigmoidf_(float x) {
    return 1.f / (1.f + __expf(-x));
}
__device__ __forceinline__ float softplus_fast_(float x) {
    return (x > 20.f) ? x : __logf(1.f + __expf(x));
}
__device__ __forceinline__ uint32_t smem_u32_(const void* p) {
    uint32_t a;
    asm("{ .reg .u64 t; cvta.to.shared.u64 t, %1; cvt.u32.u64 %0, t; }" : "=r"(a) : "l"(p));
    return a;
}
__device__ __forceinline__ uint32_t bf2_(float lo, float hi) {
    uint32_t r;
    asm("cvt.rn.bf16x2.f32 %0, %1, %2;" : "=r"(r) : "f"(hi), "f"(lo));
    return r;
}
#define LDSM4_(r0,r1,r2,r3,addr) \
    asm volatile("ldmatrix.sync.aligned.m8n8.x4.shared.b16 {%0,%1,%2,%3}, [%4];" \
        : "=r"(r0),"=r"(r1),"=r"(r2),"=r"(r3) : "r"(addr))
__device__ __forceinline__ void mma_bf16_(float* c, const uint32_t* a, const uint32_t* b) {
    asm volatile(
        "mma.sync.aligned.m16n8k16.row.col.f32.bf16.bf16.f32 "
        "{%0,%1,%2,%3}, {%4,%5,%6,%7}, {%8,%9}, {%0,%1,%2,%3};"
        : "+f"(c[0]), "+f"(c[1]), "+f"(c[2]), "+f"(c[3])
        : "r"(a[0]), "r"(a[1]), "r"(a[2]), "r"(a[3]), "r"(b[0]), "r"(b[1]));
}

// e[s] = q^(s+1) for s=0..15 via power tree
__device__ __forceinline__ void powers16_(float q, float* e) {
    float q2 = q*q, q4 = q2*q2, q8 = q4*q4;
    e[0]=q;      e[1]=q2;      e[2]=q2*q;    e[3]=q4;
    e[4]=q4*q;   e[5]=q4*q2;   e[6]=e[5]*q;  e[7]=q8;
    e[8]=q8*q;   e[9]=q8*q2;   e[10]=e[9]*q; e[11]=q8*q4;
    e[12]=e[11]*q; e[13]=e[11]*q2; e[14]=e[13]*q; e[15]=q8*q8;
}

// ---------------- bf16 GEMM w/ cp.async: C[M,N] = A[M,K] @ W[N,K]^T ----------
#define GBM 128
#define GBK 32
#define PITCH 80u
#define TILE_B (128u*PITCH)
#define STAGE_B (2u*TILE_B)
#define NSTAGE 3
#define GEMM_SMEM (NSTAGE*STAGE_B)

template<int NROWS>
__device__ __forceinline__ void cp_tile_(const __nv_bfloat16* __restrict__ G, int ld,
                                         int row0, int k0, uint32_t sb, int tid) {
    #pragma unroll
    for (int i = 0; i < NROWS/64; i++) {
        int cid = tid + i * 256;
        int row = cid >> 2;
        int c = cid & 3;
        uint32_t dst = sb + (uint32_t)row * PITCH + (uint32_t)c * 16u;
        const void* src = G + (size_t)(row0 + row) * ld + k0 + c * 8;
        asm volatile("cp.async.ca.shared.global [%0], [%1], 16;" :: "r"(dst), "l"(src));
    }
}

template<int EPI, int GN>
__global__ __launch_bounds__(256, 2) void mma_gemm_kernel(
        const __nv_bfloat16* __restrict__ A, int lda,
        const __nv_bfloat16* __restrict__ W,
        float* __restrict__ C, int ldc,
        int K, int NW) {
    constexpr int NF = GN / 32;
    extern __shared__ char smem[];
    uint32_t sbase = smem_u32_(smem);
    int tid = threadIdx.x;
    int wid = tid >> 5, lane = tid & 31;
    int g = lane >> 2, tg = lane & 3;
    int bm = blockIdx.y * GBM;
    int bn = blockIdx.x * GN;
    int wm0 = (wid & 1) * 64;
    int wn0 = (wid >> 1) * (GN / 4);

    int rr = (lane & 7) + ((lane >> 3) & 1) * 8;
    int cc = (lane >> 4);

    float acc[4][NF][4];
    #pragma unroll
    for (int mf = 0; mf < 4; mf++)
        #pragma unroll
        for (int nf = 0; nf < NF; nf++)
            #pragma unroll
            for (int r = 0; r < 4; r++) acc[mf][nf][r] = 0.f;

    const int nst = K / GBK;

    #pragma unroll
    for (int p = 0; p < NSTAGE - 1; p++) {
        uint32_t sb = sbase + (uint32_t)p * STAGE_B;
        cp_tile_<128>(A, lda, bm, p * GBK, sb, tid);
        cp_tile_<GN>(W, K,   bn, p * GBK, sb + TILE_B, tid);
        asm volatile("cp.async.commit_group;" ::: "memory");
    }

    for (int s = 0; s < nst; s++) {
        asm volatile("cp.async.wait_group 1;" ::: "memory");
        __syncthreads();
        uint32_t Sa = sbase + (uint32_t)(s % NSTAGE) * STAGE_B;
        uint32_t Sw = Sa + TILE_B;

        #pragma unroll
        for (int kk = 0; kk < 2; kk++) {
            uint32_t chunk_off = (uint32_t)(kk * 2 + cc) * 16u;
            uint32_t afr[4][4], bfr[NF][2];
            #pragma unroll
            for (int mf = 0; mf < 4; mf++) {
                uint32_t ad = Sa + (uint32_t)(wm0 + mf * 16 + rr) * PITCH + chunk_off;
                LDSM4_(afr[mf][0], afr[mf][1], afr[mf][2], afr[mf][3], ad);
            }
            #pragma unroll
            for (int nh = 0; nh < NF/2; nh++) {
                uint32_t bd = Sw + (uint32_t)(wn0 + nh * 16 + rr) * PITCH + chunk_off;
                LDSM4_(bfr[2*nh][0], bfr[2*nh+1][0], bfr[2*nh][1], bfr[2*nh+1][1], bd);
            }
            #pragma unroll
            for (int mf = 0; mf < 4; mf++)
                #pragma unroll
                for (int nf = 0; nf < NF; nf++)
                    mma_bf16_(acc[mf][nf], afr[mf], bfr[nf]);
        }

        if (s + 2 < nst) {
            uint32_t nb = sbase + (uint32_t)((s + 2) % NSTAGE) * STAGE_B;
            cp_tile_<128>(A, lda, bm, (s + 2) * GBK, nb, tid);
            cp_tile_<GN>(W, K,   bn, (s + 2) * GBK, nb + TILE_B, tid);
        }
        asm volatile("cp.async.commit_group;" ::: "memory");
    }

    #pragma unroll
    for (int mf = 0; mf < 4; mf++) {
        int gr = bm + wm0 + mf * 16 + g;
        #pragma unroll
        for (int nf = 0; nf < NF; nf++) {
            int gc = bn + wn0 + nf * 8 + 2 * tg;
            if (gc >= NW) continue;
            float2 v01 = make_float2(acc[mf][nf][0], acc[mf][nf][1]);
            float2 v23 = make_float2(acc[mf][nf][2], acc[mf][nf][3]);
            float* p0 = C + (size_t)gr * ldc + gc;
            float* p1 = C + (size_t)(gr + 8) * ldc + gc;
            if (EPI == 2) {
                float2 o0 = *reinterpret_cast<float2*>(p0);
                float2 o1 = *reinterpret_cast<float2*>(p1);
                v01.x += o0.x; v01.y += o0.y;
                v23.x += o1.x; v23.y += o1.y;
            }
            *reinterpret_cast<float2*>(p0) = v01;
            *reinterpret_cast<float2*>(p1) = v23;
        }
    }
}

// ---------------- weight conversion (all layers) -----------------------------
#define INW_E  (4*1024*256)
#define XPW_E  (4*128*512)
#define OUTW_E (4*256*512)
__global__ void wconv_kernel(const float* __restrict__ in_w,
                             const float* __restrict__ xpw,
                             const float* __restrict__ out_w) {
    int i = blockIdx.x * 256 + threadIdx.x;
    if (i < INW_E) {
        g_inw_bf[i] = __float2bfloat16(in_w[i]);
        return;
    }
    int j = i - INW_E;
    if (j < XPW_E) {
        int layer = j >> 16;
        int r = (j >> 9) & 127;
        int c = j & 511;
        float v = (r < NPROJ) ? xpw[((size_t)layer * NPROJ + r) * 512 + c] : 0.f;
        g_xpw_bf[j] = __float2bfloat16(v);
        return;
    }
    int k = j - XPW_E;
    if (k < OUTW_E) g_outw_bf[k] = __float2bfloat16(out_w[k]);
}

// ---------------- stem conv (k=3, pad=1) + relu ------------------------------
__global__ void stem_kernel(const float* __restrict__ x,
                            const float* __restrict__ sw,
                            const float* __restrict__ sb) {
    int t = blockIdx.x;
    int m = threadIdx.x;
    int b = t / LL, l = t % LL;
    __shared__ float xs[3][3];
    if (m < 9) {
        int c = m / 3, k = m % 3;
        int ll = l - 1 + k;
        xs[c][k] = (ll >= 0 && ll < LL) ? x[(b*3 + c)*LL + ll] : 0.f;
    }
    __syncthreads();
    float acc = sb[m];
    #pragma unroll
    for (int c = 0; c < 3; c++)
        #pragma unroll
        for (int k = 0; k < 3; k++)
            acc = fmaf(xs[c][k], sw[(m*3 + c)*3 + k], acc);
    g_h[t*DM + m] = fmaxf(acc, 0.f);
}

// ---------------- layernorm -> bf16, warp-per-token --------------------------
__device__ __forceinline__ float warp_sum_(float v) {
    #pragma unroll
    for (int o = 16; o; o >>= 1) v += __shfl_xor_sync(0xffffffffu, v, o);
    return v;
}
__global__ __launch_bounds__(256) void ln_kernel(const float* __restrict__ in,
                                                 const float* __restrict__ g,
                                                 const float* __restrict__ b) {
    int wid = threadIdx.x >> 5, lane = threadIdx.x & 31;
    int t = blockIdx.x * 8 + wid;
    const float* row = in + (size_t)t * DM + lane * 8;
    float4 v0 = *reinterpret_cast<const float4*>(row);
    float4 v1 = *reinterpret_cast<const float4*>(row + 4);
    float s = v0.x+v0.y+v0.z+v0.w + v1.x+v1.y+v1.z+v1.w;
    float mean = warp_sum_(s) * (1.f / DM);
    float d0 = v0.x-mean, d1 = v0.y-mean, d2 = v0.z-mean, d3 = v0.w-mean;
    float d4 = v1.x-mean, d5 = v1.y-mean, d6 = v1.z-mean, d7 = v1.w-mean;
    float q = d0*d0+d1*d1+d2*d2+d3*d3+d4*d4+d5*d5+d6*d6+d7*d7;
    float rstd = rsqrtf(warp_sum_(q) * (1.f / DM) + 1e-5f);
    float4 g0 = *reinterpret_cast<const float4*>(g + lane * 8);
    float4 g1 = *reinterpret_cast<const float4*>(g + lane * 8 + 4);
    float4 b0 = *reinterpret_cast<const float4*>(b + lane * 8);
    float4 b1 = *reinterpret_cast<const float4*>(b + lane * 8 + 4);
    uint4 o;
    o.x = bf2_(d0*rstd*g0.x + b0.x, d1*rstd*g0.y + b0.y);
    o.y = bf2_(d2*rstd*g0.z + b0.z, d3*rstd*g0.w + b0.w);
    o.z = bf2_(d4*rstd*g1.x + b1.x, d5*rstd*g1.y + b1.y);
    o.w = bf2_(d6*rstd*g1.z + b1.z, d7*rstd*g1.w + b1.w);
    *reinterpret_cast<uint4*>(g_xn_bf + (size_t)t * DM + lane * 8) = o;
}

// ---------------- causal depthwise conv (k=4, left pad 3) + silu -------------
// (R14 scalar version — proven 32us/layer)
__global__ void conv_silu_kernel(const float* __restrict__ cw,
                                 const float* __restrict__ cb) {
    int idx = blockIdx.x * blockDim.x + threadIdx.x;
    if (idx >= TOK*DI) return;
    int d = idx % DI;
    int t = idx / DI;
    int l = t % LL;
    float acc = cb[d];
    #pragma unroll
    for (int k = 0; k < 4; k++) {
        int ls = l - 3 + k;
        if (ls >= 0)
            acc = fmaf(g_xz[(size_t)(t - 3 + k)*(2*DI) + d], cw[d*4 + k], acc);
    }
    float r = acc * sigmoidf_(acc);
    g_u[idx] = r;
    g_u_bf[idx] = __float2bfloat16(r);
}

// ---------------- scan pass 1: whole-segment smem staging + fused delta ------
// grid (DI/256, BN, NSEG), 256 threads; thread-per-d, SEGL=32.
// g_proj rows for a segment are contiguous -> one coalesced float4 stage,
// ONE __syncthreads per CTA.
__global__ __launch_bounds__(256) void scan1_kernel(const float* __restrict__ Alog,
                                                    const float* __restrict__ dtw,
                                                    const float* __restrict__ dtb) {
    __shared__ __align__(16) float sP[SEGL*NPROJ];   // 6 KB
    int d = blockIdx.x * 256 + threadIdx.x;
    int b = blockIdx.y;
    int seg = blockIdx.z;
    int tid = threadIdx.x;
    int t0 = b * LL + seg * SEGL;

    // stage whole segment's proj rows (SEGL*NPROJ = 1536 floats = 384 float4)
    {
        const float4* src = reinterpret_cast<const float4*>(g_proj + (size_t)t0 * NPROJ);
        float4* dst = reinterpret_cast<float4*>(sP);
        #pragma unroll
        for (int r = 0; r < 2; r++) {
            int i = tid + r * 256;
            if (i < SEGL*NPROJ/4) dst[i] = src[i];
        }
    }

    float A[DS], wdt[DTR];
    bool fast = true;
    #pragma unroll
    for (int s4 = 0; s4 < DS; s4 += 4) {
        float4 av = *reinterpret_cast<const float4*>(Alog + d*DS + s4);
        A[s4] = -__expf(av.x); A[s4+1] = -__expf(av.y);
        A[s4+2] = -__expf(av.z); A[s4+3] = -__expf(av.w);
        fast = fast && fabsf(A[s4] + (float)(s4+1)) < 1e-3f
                    && fabsf(A[s4+1] + (float)(s4+2)) < 1e-3f
                    && fabsf(A[s4+2] + (float)(s4+3)) < 1e-3f
                    && fabsf(A[s4+3] + (float)(s4+4)) < 1e-3f;
    }
    fast = __all_sync(0xffffffffu, fast);
    #pragma unroll
    for (int r4 = 0; r4 < DTR; r4 += 4) {
        float4 wv = *reinterpret_cast<const float4*>(dtw + d*DTR + r4);
        wdt[r4] = wv.x; wdt[r4+1] = wv.y; wdt[r4+2] = wv.z; wdt[r4+3] = wv.w;
    }
    float bdt = dtb[d];

    float h[DS];
    #pragma unroll
    for (int s = 0; s < DS; s++) h[s] = 0.f;
    float sumd = 0.f;

    __syncthreads();

    for (int c0 = 0; c0 < SEGL; c0 += 8) {
        float uc[8];
        #pragma unroll
        for (int i = 0; i < 8; i++)
            uc[i] = g_u[(size_t)(t0 + c0 + i)*DI + d];
        #pragma unroll
        for (int i = 0; i < 8; i++) {
            const float* row = sP + (c0 + i) * NPROJ;
            float draw = bdt;
            #pragma unroll
            for (int r = 0; r < DTR; r++) draw = fmaf(row[r], wdt[r], draw);
            float dlt = softplus_fast_(draw);
            g_delta[(size_t)(t0 + c0 + i)*DI + d] = dlt;
            float du = dlt * uc[i];
            sumd += dlt;
            float e[DS];
            if (fast) powers16_(__expf(-dlt), e);
            else {
                #pragma unroll
                for (int s = 0; s < DS; s++) e[s] = __expf(dlt * A[s]);
            }
            const float* Brow = row + DTR;
            #pragma unroll
            for (int s = 0; s < DS; s++)
                h[s] = fmaf(h[s], e[s], du * Brow[s]);
        }
    }

    size_t idx = ((size_t)b * NSEG + seg) * DI + d;
    float* H = g_hseg + idx * DS;
    #pragma unroll
    for (int s4 = 0; s4 < DS; s4 += 4)
        *reinterpret_cast<float4*>(H + s4) =
            make_float4(h[s4], h[s4+1], h[s4+2], h[s4+3]);
    g_sumd[idx] = sumd;
}

// ---------------- scan combine: prefix over segments -------------------------
__global__ __launch_bounds__(256) void scomb_kernel(const float* __restrict__ Alog) {
    int i = blockIdx.x * 256 + threadIdx.x;
    int b = i >> 9, d = i & 511;

    float A[DS];
    bool fast = true;
    #pragma unroll
    for (int s4 = 0; s4 < DS; s4 += 4) {
        float4 av = *reinterpret_cast<const float4*>(Alog + d*DS + s4);
        A[s4] = -__expf(av.x); A[s4+1] = -__expf(av.y);
        A[s4+2] = -__expf(av.z); A[s4+3] = -__expf(av.w);
        fast = fast && fabsf(A[s4] + (float)(s4+1)) < 1e-3f
                    && fabsf(A[s4+1] + (float)(s4+2)) < 1e-3f
                    && fabsf(A[s4+2] + (float)(s4+3)) < 1e-3f
                    && fabsf(A[s4+3] + (float)(s4+4)) < 1e-3f;
    }
    fast = __all_sync(0xffffffffu, fast);

    float carry[DS];
    #pragma unroll
    for (int s = 0; s < DS; s++) carry[s] = 0.f;

    for (int j = 0; j < NSEG; j++) {
        size_t idx = ((size_t)b * NSEG + j) * DI + d;
        float* I = g_hinit + idx * DS;
        #pragma unroll
        for (int s4 = 0; s4 < DS; s4 += 4)
            *reinterpret_cast<float4*>(I + s4) =
                make_float4(carry[s4], carry[s4+1], carry[s4+2], carry[s4+3]);
        float sd = g_sumd[idx];
        float e[DS];
        if (fast) powers16_(__expf(-sd), e);
        else {
            #pragma unroll
            for (int s = 0; s < DS; s++) e[s] = __expf(sd * A[s]);
        }
        const float* H = g_hseg + idx * DS;
        #pragma unroll
        for (int s4 = 0; s4 < DS; s4 += 4) {
            float4 hv = *reinterpret_cast<const float4*>(H + s4);
            carry[s4]   = fmaf(carry[s4],   e[s4],   hv.x);
            carry[s4+1] = fmaf(carry[s4+1], e[s4+1], hv.y);
            carry[s4+2] = fmaf(carry[s4+2], e[s4+2], hv.z);
            carry[s4+3] = fmaf(carry[s4+3], e[s4+3], hv.w);
        }
    }
}

// ---------------- scan pass 2: whole-segment staging, rescan, emit y ---------
__global__ __launch_bounds__(256) void scan2_kernel(const float* __restrict__ Alog,
                                                    const float* __restrict__ Dp) {
    __shared__ __align__(16) float sP[SEGL*NPROJ];   // 6 KB
    int d = blockIdx.x * 256 + threadIdx.x;
    int b = blockIdx.y;
    int seg = blockIdx.z;
    int tid = threadIdx.x;
    int t0 = b * LL + seg * SEGL;

    {
        const float4* src = reinterpret_cast<const float4*>(g_proj + (size_t)t0 * NPROJ);
        float4* dst = reinterpret_cast<float4*>(sP);
        #pragma unroll
        for (int r = 0; r < 2; r++) {
            int i = tid + r * 256;
            if (i < SEGL*NPROJ/4) dst[i] = src[i];
        }
    }

    float A[DS];
    bool fast = true;
    #pragma unroll
    for (int s4 = 0; s4 < DS; s4 += 4) {
        float4 av = *reinterpret_cast<const float4*>(Alog + d*DS + s4);
        A[s4] = -__expf(av.x); A[s4+1] = -__expf(av.y);
        A[s4+2] = -__expf(av.z); A[s4+3] = -__expf(av.w);
        fast = fast && fabsf(A[s4] + (float)(s4+1)) < 1e-3f
                    && fabsf(A[s4+1] + (float)(s4+2)) < 1e-3f
                    && fabsf(A[s4+2] + (float)(s4+3)) < 1e-3f
                    && fabsf(A[s4+3] + (float)(s4+4)) < 1e-3f;
    }
    fast = __all_sync(0xffffffffu, fast);
    float Dd = Dp[d];

    float h[DS];
    {
        size_t idx = ((size_t)b * NSEG + seg) * DI + d;
        const float* I = g_hinit + idx * DS;
        #pragma unroll
        for (int s4 = 0; s4 < DS; s4 += 4) {
            float4 hv = *reinterpret_cast<const float4*>(I + s4);
            h[s4] = hv.x; h[s4+1] = hv.y; h[s4+2] = hv.z; h[s4+3] = hv.w;
        }
    }

    __syncthreads();

    for (int c0 = 0; c0 < SEGL; c0 += 8) {
        float dc[8], uc[8], zc[8];
        #pragma unroll
        for (int i = 0; i < 8; i++) {
            size_t t = (size_t)(t0 + c0 + i);
            dc[i] = g_delta[t*DI + d];
            uc[i] = g_u[t*DI + d];
            zc[i] = g_xz[t*2*DI + DI + d];
        }
        #pragma unroll
        for (int i = 0; i < 8; i++) {
            float dlt = dc[i], uu = uc[i];
            float du = dlt * uu;
            float e[DS];
            if (fast) powers16_(__expf(-dlt), e);
            else {
                #pragma unroll
                for (int s = 0; s < DS; s++) e[s] = __expf(dlt * A[s]);
            }
            const float* Brow = sP + (c0 + i) * NPROJ + DTR;
            const float* Crow = Brow + DS;
            float y = 0.f;
            #pragma unroll
            for (int s = 0; s < DS; s++) {
                h[s] = fmaf(h[s], e[s], du * Brow[s]);
                y = fmaf(h[s], Crow[s], y);
            }
            y = fmaf(uu, Dd, y);
            float zz = zc[i];
            y *= zz * sigmoidf_(zz);
            g_y_bf[(size_t)(t0 + c0 + i)*DI + d] = __float2bfloat16(y);
        }
    }
}

// ---------------- final LN + head projection + sigmoid (warp/token) ----------
__global__ __launch_bounds__(256) void head_kernel(const float* __restrict__ g,
                                                   const float* __restrict__ b,
                                                   const float* __restrict__ hw,
                                                   const float* __restrict__ hb,
                                                   float* __restrict__ out) {
    int wid = threadIdx.x >> 5, lane = threadIdx.x & 31;
    int t = blockIdx.x * 8 + wid;
    const float* row = g_h + (size_t)t * DM + lane * 8;
    float4 v0 = *reinterpret_cast<const float4*>(row);
    float4 v1 = *reinterpret_cast<const float4*>(row + 4);
    float s = v0.x+v0.y+v0.z+v0.w + v1.x+v1.y+v1.z+v1.w;
    float mean = warp_sum_(s) * (1.f / DM);
    float d0 = v0.x-mean, d1 = v0.y-mean, d2 = v0.z-mean, d3 = v0.w-mean;
    float d4 = v1.x-mean, d5 = v1.y-mean, d6 = v1.z-mean, d7 = v1.w-mean;
    float q = d0*d0+d1*d1+d2*d2+d3*d3+d4*d4+d5*d5+d6*d6+d7*d7;
    float rstd = rsqrtf(warp_sum_(q) * (1.f / DM) + 1e-5f);
    float4 g0 = *reinterpret_cast<const float4*>(g + lane * 8);
    float4 g1 = *reinterpret_cast<const float4*>(g + lane * 8 + 4);
    float4 b0 = *reinterpret_cast<const float4*>(b + lane * 8);
    float4 b1 = *reinterpret_cast<const float4*>(b + lane * 8 + 4);
    float4 w0 = *reinterpret_cast<const float4*>(hw + lane * 8);
    float4 w1 = *reinterpret_cast<const float4*>(hw + lane * 8 + 4);
    float dot =
        (d0*rstd*g0.x + b0.x)*w0.x + (d1*rstd*g0.y + b0.y)*w0.y +
        (d2*rstd*g0.z + b0.z)*w0.z + (d3*rstd*g0.w + b0.w)*w0.w +
        (d4*rstd*g1.x + b1.x)*w1.x + (d5*rstd*g1.y + b1.y)*w1.y +
        (d6*rstd*g1.z + b1.z)*w1.z + (d7*rstd*g1.w + b1.w)*w1.w;
    float tot = warp_sum_(dot);
    if (lane == 0) out[t] = sigmoidf_(tot + hb[0]);
}

// ---------------- host launcher ----------------------------------------------
extern "C" void kernel_launch(void* const* d_in, const int* in_sizes, int n_in,
                              void* d_out, int out_size) {
    const float* x       = (const float*)d_in[0];
    const float* stem_w  = (const float*)d_in[1];
    const float* stem_b  = (const float*)d_in[2];
    const float* norm_g  = (const float*)d_in[3];
    const float* norm_b  = (const float*)d_in[4];
    const float* in_w    = (const float*)d_in[5];
    const float* conv_w  = (const float*)d_in[6];
    const float* conv_b  = (const float*)d_in[7];
    const float* xpw     = (const float*)d_in[8];
    const float* dtw     = (const float*)d_in[9];
    const float* dtb     = (const float*)d_in[10];
    const float* A_log   = (const float*)d_in[11];
    const float* Dp      = (const float*)d_in[12];
    const float* out_w   = (const float*)d_in[13];
    const float* fn_g    = (const float*)d_in[14];
    const float* fn_b    = (const float*)d_in[15];
    const float* head_w  = (const float*)d_in[16];
    const float* head_b  = (const float*)d_in[17];
    float* out = (float*)d_out;

    float *p_h, *p_xz, *p_u, *p_proj;
    __nv_bfloat16 *p_xn_bf, *p_u_bf, *p_y_bf, *p_inw, *p_xpw, *p_outw;
    cudaGetSymbolAddress((void**)&p_h,     g_h);
    cudaGetSymbolAddress((void**)&p_xz,    g_xz);
    cudaGetSymbolAddress((void**)&p_u,     g_u);
    cudaGetSymbolAddress((void**)&p_proj,  g_proj);
    cudaGetSymbolAddress((void**)&p_xn_bf, g_xn_bf);
    cudaGetSymbolAddress((void**)&p_u_bf,  g_u_bf);
    cudaGetSymbolAddress((void**)&p_y_bf,  g_y_bf);
    cudaGetSymbolAddress((void**)&p_inw,   g_inw_bf);
    cudaGetSymbolAddress((void**)&p_xpw,   g_xpw_bf);
    cudaGetSymbolAddress((void**)&p_outw,  g_outw_bf);

    cudaFuncSetAttribute((const void*)mma_gemm_kernel<0,128>,
                         cudaFuncAttributeMaxDynamicSharedMemorySize, GEMM_SMEM);
    cudaFuncSetAttribute((const void*)mma_gemm_kernel<2,128>,
                         cudaFuncAttributeMaxDynamicSharedMemorySize, GEMM_SMEM);
    cudaFuncSetAttribute((const void*)mma_gemm_kernel<0,64>,
                         cudaFuncAttributeMaxDynamicSharedMemorySize, GEMM_SMEM);

    wconv_kernel<<<(INW_E + XPW_E + OUTW_E)/256, 256>>>(in_w, xpw, out_w);
    stem_kernel<<<TOK, 256>>>(x, stem_w, stem_b);

    for (int i = 0; i < 4; i++) {
        ln_kernel<<<TOK/8, 256>>>(p_h, norm_g + i*DM, norm_b + i*DM);

        // in_proj: [TOK,1024] = xn @ W^T
        {
            dim3 grid((2*DI)/128, TOK/GBM);
            mma_gemm_kernel<0,128><<<grid, 256, GEMM_SMEM>>>(
                p_xn_bf, DM, p_inw + (size_t)i*1024*256, p_xz, 2*DI, DM, 2*DI);
        }

        conv_silu_kernel<<<(TOK*DI + 255)/256, 256>>>(conv_w + (size_t)i*DI*4,
                                                      conv_b + (size_t)i*DI);

        // x_proj: [TOK,48] = u @ xw^T (64-wide tile, W padded rows)
        {
            dim3 grid(1, TOK/GBM);
            mma_gemm_kernel<0,64><<<grid, 256, GEMM_SMEM>>>(
                p_u_bf, DI, p_xpw + (size_t)i*128*512, p_proj, NPROJ, DI, NPROJ);
        }

        // chunked parallel scan: pass1 (fused delta) -> combine -> pass2
        {
            dim3 grid1(DI/256, BN, NSEG);
            scan1_kernel<<<grid1, 256>>>(A_log + (size_t)i*DI*DS,
                                         dtw + (size_t)i*DI*DTR,
                                         dtb + (size_t)i*DI);
            scomb_kernel<<<BN*DI/256, 256>>>(A_log + (size_t)i*DI*DS);
            scan2_kernel<<<grid1, 256>>>(A_log + (size_t)i*DI*DS, Dp + (size_t)i*DI);
        }

        // out proj + residual: h += y @ ow^T
        {
            dim3 grid(DM/128, TOK/GBM);
            mma_gemm_kernel<2,128><<<grid, 256, GEMM_SMEM>>>(
                p_y_bf, DI, p_outw + (size_t)i*256*512, p_h, DM, DI, DM);
        }
    }

    head_kernel<<<TOK/8, 256>>>(fn_g, fn_b, head_w, head_b, out);
    (void)in_sizes; (void)n_in; (void)out_size;
}